// round 10
// baseline (speedup 1.0000x reference)
#include <cuda_runtime.h>
#include <cuda_fp16.h>
#include <cstdint>

#define LQ 152        // qo_kernel smem stride (halves)
#define SNU 72        // nf/wt_k/wt_v u32 stride (144 halves), XOR-4 swizzled
#define SNH 144
#define SSU 68        // kv u32 stride (136 halves)
#define SSH 136
#define SLU 66        // wt_l/x1h u32 stride (132 halves)
#define SLH 132

// smem byte offsets
#define OFF_WK  0
#define OFF_WV  36864
#define OFF_NF  73728
#define OFF_WL  110592
#define OFF_KV0 144384
#define OFF_KV1 179200
#define OFF_X1H 214016
#define OFF_QO  216128
#define OFF_X1F 220224
#define OFF_YB  224320
#define OFF_CB  228416
#define SMEM_TOT 232000

__device__ float g_QO[(size_t)100000 * 128];

__device__ __forceinline__ void mma16816(float* d, const unsigned* a, unsigned b0, unsigned b1) {
    asm volatile(
        "mma.sync.aligned.m16n8k16.row.col.f32.f16.f16.f32 "
        "{%0,%1,%2,%3}, {%4,%5,%6,%7}, {%8,%9}, {%0,%1,%2,%3};\n"
        : "+f"(d[0]), "+f"(d[1]), "+f"(d[2]), "+f"(d[3])
        : "r"(a[0]), "r"(a[1]), "r"(a[2]), "r"(a[3]), "r"(b0), "r"(b1));
}

// warp w computes rows w*16..+15 (all 128 cols) of BOTH K and V projections.
// A fragments (nf) shared between the two B operands.
__device__ __forceinline__ void gemm_regs(const char* sm, float (&aK)[16][4], float (&aV)[16][4],
                                          int w8, int gid, int tig) {
    const unsigned* nfU = (const unsigned*)(sm + OFF_NF);
    const unsigned* wkU = (const unsigned*)(sm + OFF_WK);
    const unsigned* wvU = (const unsigned*)(sm + OFF_WV);
    int sw = ((gid >> 2) & 1) * 4;
#pragma unroll
    for (int i = 0; i < 16; i++)
#pragma unroll
        for (int l = 0; l < 4; l++) { aK[i][l] = 0.f; aV[i][l] = 0.f; }
    for (int ch = 0; ch < 9; ch++) {
        int kr = ch * 8 + tig;
        int kc = kr ^ sw, kc4 = (kr + 4) ^ sw;
        const unsigned* p0 = nfU + (w8 * 16 + gid) * SNU;
        const unsigned* p1 = p0 + 8 * SNU;
        unsigned A[4] = {p0[kc], p1[kc], p0[kc4], p1[kc4]};
#pragma unroll
        for (int nt = 0; nt < 16; nt++) {
            const unsigned* pk = wkU + (nt * 8 + gid) * SNU;
            mma16816(aK[nt], A, pk[kc], pk[kc4]);
            const unsigned* pv = wvU + (nt * 8 + gid) * SNU;
            mma16816(aV[nt], A, pv[kc], pv[kc4]);
        }
    }
}

__device__ __forceinline__ void store_kv(char* sm, const float (&aK)[16][4], const float (&aV)[16][4],
                                         const float* kb, const float* vb, int w8, int gid, int tig) {
    half* k0 = (half*)(sm + OFF_KV0);
    half* k1 = (half*)(sm + OFF_KV1);
    int r = w8 * 16 + gid;
#pragma unroll
    for (int nt = 0; nt < 16; nt++) {
        int c = nt * 8 + 2 * tig;
        float b0k = kb[c], b1k = kb[c + 1], b0v = vb[c], b1v = vb[c + 1];
        *(half2*)(k0 + r * SSH + c)       = __floats2half2_rn(aK[nt][0] + b0k, aK[nt][1] + b1k);
        *(half2*)(k0 + (r + 8) * SSH + c) = __floats2half2_rn(aK[nt][2] + b0k, aK[nt][3] + b1k);
        *(half2*)(k1 + r * SSH + c)       = __floats2half2_rn(aV[nt][0] + b0v, aV[nt][1] + b1v);
        *(half2*)(k1 + (r + 8) * SSH + c) = __floats2half2_rn(aV[nt][2] + b0v, aV[nt][3] + b1v);
    }
}

__device__ __forceinline__ void load_nf_direct(char* sm, const float* knn, const float* xyz,
                                               int blk, int n16, int tid) {
    unsigned* nfU = (unsigned*)(sm + OFF_NF);
    for (int i4 = tid; i4 < 4096; i4 += 256) {
        int r = i4 >> 5, c4 = i4 & 31;
        int src = min(blk * 128 + r, n16 - 1);
        float4 v = ((const float4*)knn)[src * 32 + c4];
        int sw = ((r >> 2) & 1) * 4;
        half2* d = (half2*)(nfU + r * SNU + ((c4 * 2) ^ sw));
        d[0] = __floats2half2_rn(v.x, v.y);
        d[1] = __floats2half2_rn(v.z, v.w);
    }
    if (tid < 128) {
        half* nf = (half*)(sm + OFF_NF);
        int src = min(blk * 128 + tid, n16 - 1);
        int swh = ((tid >> 2) & 1) * 8;
        nf[tid * SNH + (128 ^ swh)] = __float2half(xyz[src * 3 + 0]);
        nf[tid * SNH + (129 ^ swh)] = __float2half(xyz[src * 3 + 1]);
        nf[tid * SNH + (130 ^ swh)] = __float2half(xyz[src * 3 + 2]);
    }
}

// one warp normalizes one 128-float smem row in place
__device__ __forceinline__ void layernorm_row(float* v, const float* g, const float* b, int lane) {
    float4 val = ((float4*)v)[lane];
    float s = val.x + val.y + val.z + val.w;
    float s2 = val.x * val.x + val.y * val.y + val.z * val.z + val.w * val.w;
#pragma unroll
    for (int o = 16; o; o >>= 1) {
        s  += __shfl_xor_sync(0xffffffffu, s, o);
        s2 += __shfl_xor_sync(0xffffffffu, s2, o);
    }
    float m = s * (1.f / 128.f);
    float inv = rsqrtf(s2 * (1.f / 128.f) - m * m + 1e-5f);
    int c = lane * 4;
    float o0 = (val.x - m) * inv * g[c] + b[c];
    float o1 = (val.y - m) * inv * g[c + 1] + b[c + 1];
    float o2 = (val.z - m) * inv * g[c + 2] + b[c + 2];
    float o3 = (val.w - m) * inv * g[c + 3] + b[c + 3];
    ((float4*)v)[lane] = make_float4(o0, o1, o2, o3);
}

// ---------------- Kernel 1: QO = x @ q_w + q_b ----------------
__global__ void __launch_bounds__(256)
qo_kernel(const float* __restrict__ x, const float* __restrict__ q_w,
          const float* __restrict__ q_b, int n) {
    extern __shared__ char smraw[];
    half* xs = (half*)smraw;
    half* wt = xs + 128 * LQ;
    float* qb = (float*)(wt + 128 * LQ);
    int tid = threadIdx.x;
    int base = blockIdx.x * 128;
    {
        half2 z = __floats2half2_rn(0.f, 0.f);
        half2* p = (half2*)smraw;
        for (int i = tid; i < 128 * LQ; i += 256) p[i] = z;
    }
    __syncthreads();
    for (int i = tid; i < 128 * 128; i += 256) {
        int j = i >> 7, c = i & 127;
        wt[c * LQ + j] = __float2half(q_w[i]);
    }
    for (int i4 = tid; i4 < 4096; i4 += 256) {
        int r = i4 >> 5, c4 = i4 & 31;
        int src = min(base + r, n - 1);
        float4 v = ((const float4*)x)[src * 32 + c4];
        half2* d = (half2*)(xs + r * LQ + c4 * 4);
        d[0] = __floats2half2_rn(v.x, v.y);
        d[1] = __floats2half2_rn(v.z, v.w);
    }
    if (tid < 128) qb[tid] = q_b[tid];
    __syncthreads();

    int w = tid >> 5, lane = tid & 31, gid = lane >> 2, tig = lane & 3;
    int r0 = (w & 3) * 32, c0 = (w >> 2) * 64;
    float acc[2][8][4];
#pragma unroll
    for (int i = 0; i < 2; i++)
#pragma unroll
        for (int j = 0; j < 8; j++)
#pragma unroll
            for (int l = 0; l < 4; l++) acc[i][j][l] = 0.f;
    for (int ch = 0; ch < 8; ch++) {
        int kc = ch * 8 + tig;
        unsigned a[2][4];
#pragma unroll
        for (int mt = 0; mt < 2; mt++) {
            const unsigned* p0 = (const unsigned*)(xs + (r0 + mt * 16 + gid) * LQ);
            const unsigned* p1 = (const unsigned*)(xs + (r0 + mt * 16 + gid + 8) * LQ);
            a[mt][0] = p0[kc];     a[mt][1] = p1[kc];
            a[mt][2] = p0[kc + 4]; a[mt][3] = p1[kc + 4];
        }
#pragma unroll
        for (int nt = 0; nt < 8; nt++) {
            const unsigned* pb = (const unsigned*)(wt + (c0 + nt * 8 + gid) * LQ);
            unsigned b0 = pb[kc], b1 = pb[kc + 4];
            mma16816(acc[0][nt], a[0], b0, b1);
            mma16816(acc[1][nt], a[1], b0, b1);
        }
    }
#pragma unroll
    for (int mt = 0; mt < 2; mt++)
#pragma unroll
        for (int nt = 0; nt < 8; nt++) {
            int r = r0 + mt * 16 + gid, c = c0 + nt * 8 + 2 * tig;
            float* d = acc[mt][nt];
            if (base + r < n) {
                g_QO[(size_t)(base + r) * 128 + c]     = d[0] + qb[c];
                g_QO[(size_t)(base + r) * 128 + c + 1] = d[1] + qb[c + 1];
            }
            if (base + r + 8 < n) {
                g_QO[(size_t)(base + r + 8) * 128 + c]     = d[2] + qb[c];
                g_QO[(size_t)(base + r + 8) * 128 + c + 1] = d[3] + qb[c + 1];
            }
        }
}

// ---------------- Kernel 2: fused gemm+epilogue, reg-resident accumulators ----------------
__global__ void __launch_bounds__(256, 1)
tb_main(const float* __restrict__ x,
        const float* __restrict__ knn, const float* __restrict__ xyz,
        const float* __restrict__ k_w, const float* __restrict__ k_b,
        const float* __restrict__ v_w, const float* __restrict__ v_b,
        const float* __restrict__ lin_w, const float* __restrict__ lin_b,
        const float* __restrict__ l1g, const float* __restrict__ l1b,
        const float* __restrict__ l2g, const float* __restrict__ l2b,
        float* __restrict__ out, int n)
{
    extern __shared__ __align__(16) char sm[];
    int tid = threadIdx.x;
    int w8 = tid >> 5, lane = tid & 31, gid = lane >> 2, tig = lane & 3;
    float* qoY = (float*)(sm + OFF_QO);
    float* x1f = (float*)(sm + OFF_X1F);
    float* yb  = (float*)(sm + OFF_YB);
    float* cb  = (float*)(sm + OFF_CB);
    half*  x1h = (half*)(sm + OFF_X1H);

    // zero wt_k/wt_v/nf (K-padding cols must stay 0)
    {
        float4 z4 = make_float4(0.f, 0.f, 0.f, 0.f);
        for (int i = tid; i < 110592 / 16; i += 256) ((float4*)sm)[i] = z4;
    }
    __syncthreads();
    for (int i = tid; i < 131 * 128; i += 256) {
        int j = i >> 7, c = i & 127;
        int swh = ((c >> 2) & 1) * 8;
        ((half*)(sm + OFF_WK))[c * SNH + (j ^ swh)] = __float2half(k_w[i]);
        ((half*)(sm + OFF_WV))[c * SNH + (j ^ swh)] = __float2half(v_w[i]);
        if (j < 128) ((half*)(sm + OFF_WL))[c * SLH + j] = __float2half(lin_w[i]);
    }
    if (tid < 128) {
        cb[tid]       = k_b[tid];   cb[128 + tid] = v_b[tid];
        cb[256 + tid] = lin_b[tid]; cb[384 + tid] = l1g[tid];
        cb[512 + tid] = l1b[tid];   cb[640 + tid] = l2g[tid];
        cb[768 + tid] = l2b[tid];
    }
    const float *kb = cb, *vb = cb + 128, *lb = cb + 256;
    const float *g1 = cb + 384, *b1 = cb + 512, *g2 = cb + 640, *b2 = cb + 768;

    int nblk = (n + 7) >> 3;
    int n16 = n * 16;
    int G = gridDim.x;
    int blk0 = blockIdx.x;
    bool act = blk0 < nblk;

    float aK[16][4], aV[16][4];

    // ---- prologue: nf<-b0, Q/x<-b0; gemm(b0)->kv; nf<-b1 ----
    if (act) {
        load_nf_direct(sm, knn, xyz, blk0, n16, tid);
        int np = min(blk0 * 8 + (tid >> 5), n - 1);
        ((float4*)qoY)[tid] = ((const float4*)g_QO)[np * 32 + (tid & 31)];
        ((float4*)x1f)[tid] = ((const float4*)x)[np * 32 + (tid & 31)];
    }
    __syncthreads();
    if (act) gemm_regs(sm, aK, aV, w8, gid, tig);
    __syncthreads();
    if (act) store_kv(sm, aK, aV, kb, vb, w8, gid, tig);
    if (blk0 + G < nblk) load_nf_direct(sm, knn, xyz, blk0 + G, n16, tid);
    __syncthreads();

    for (int blk = blk0; blk < nblk; blk += G) {
        int nb1 = blk + G, nb2 = blk + 2 * G;
        bool h1 = nb1 < nblk, h2 = nb2 < nblk;
        int r5 = tid >> 5, c4t = tid & 31;

        // ======== PHASE X (barrier-free): prefetch issue + gemm(nb1) + epilogue(blk) ========
        float4 pfA[8], pq, px;
        float xz0 = 0.f, xz1 = 0.f, xz2 = 0.f;
        if (h2) {
#pragma unroll
            for (int k = 0; k < 8; k++) {
                int src = min(nb2 * 128 + k * 8 + r5, n16 - 1);
                pfA[k] = ((const float4*)knn)[src * 32 + c4t];
            }
            if (tid < 128) {
                int src = min(nb2 * 128 + tid, n16 - 1);
                xz0 = xyz[src * 3 + 0]; xz1 = xyz[src * 3 + 1]; xz2 = xyz[src * 3 + 2];
            }
        }
        if (h1) {
            int np = min(nb1 * 8 + (tid >> 5), n - 1);
            pq = ((const float4*)g_QO)[np * 32 + (tid & 31)];
            px = ((const float4*)x)[np * 32 + (tid & 31)];
        }

        if (h1) gemm_regs(sm, aK, aV, w8, gid, tig);

        // ---- epilogue for blk: warp w8 = point p ----
        {
            int p = w8;
            int kk = lane >> 1, hf = lane & 1;
            const half* kv0 = (const half*)(sm + OFF_KV0);
            const half* kv1 = (const half*)(sm + OFF_KV1);
            float aN[4];
#pragma unroll
            for (int h = 0; h < 4; h++) {
                const float4* qp = (const float4*)(qoY + p * 128 + h * 32 + hf * 16);
                float4 q0 = qp[0], q1 = qp[1], q2 = qp[2], q3 = qp[3];
                const half2* kp = (const half2*)(kv0 + (p * 16 + h * 4 + (kk >> 2)) * SSH
                                                 + (kk & 3) * 32 + hf * 16);
                float s = 0.f;
                float2 kf;
                kf = __half22float2(kp[0]); s = fmaf(q0.x, kf.x, s); s = fmaf(q0.y, kf.y, s);
                kf = __half22float2(kp[1]); s = fmaf(q0.z, kf.x, s); s = fmaf(q0.w, kf.y, s);
                kf = __half22float2(kp[2]); s = fmaf(q1.x, kf.x, s); s = fmaf(q1.y, kf.y, s);
                kf = __half22float2(kp[3]); s = fmaf(q1.z, kf.x, s); s = fmaf(q1.w, kf.y, s);
                kf = __half22float2(kp[4]); s = fmaf(q2.x, kf.x, s); s = fmaf(q2.y, kf.y, s);
                kf = __half22float2(kp[5]); s = fmaf(q2.z, kf.x, s); s = fmaf(q2.w, kf.y, s);
                kf = __half22float2(kp[6]); s = fmaf(q3.x, kf.x, s); s = fmaf(q3.y, kf.y, s);
                kf = __half22float2(kp[7]); s = fmaf(q3.z, kf.x, s); s = fmaf(q3.w, kf.y, s);
                s += __shfl_xor_sync(0xffffffffu, s, 1);
                float m = s;
                m = fmaxf(m, __shfl_xor_sync(0xffffffffu, m, 2));
                m = fmaxf(m, __shfl_xor_sync(0xffffffffu, m, 4));
                m = fmaxf(m, __shfl_xor_sync(0xffffffffu, m, 8));
                m = fmaxf(m, __shfl_xor_sync(0xffffffffu, m, 16));
                float e = __expf((s - m) * 0.08838834764831845f);
                float sum = e;
                sum += __shfl_xor_sync(0xffffffffu, sum, 2);
                sum += __shfl_xor_sync(0xffffffffu, sum, 4);
                sum += __shfl_xor_sync(0xffffffffu, sum, 8);
                sum += __shfl_xor_sync(0xffffffffu, sum, 16);
                aN[h] = e / sum;
            }
            // att_feat: lane = d column
            float af[4];
#pragma unroll
            for (int h = 0; h < 4; h++) {
                const half* vbase = kv1 + (p * 16 + h * 4) * SSH + lane;
                float acc = 0.f;
#pragma unroll
                for (int kx = 0; kx < 16; kx++) {
                    float a = __shfl_sync(0xffffffffu, aN[h], kx * 2);
                    acc = fmaf(a, __half2float(vbase[(kx >> 2) * SSH + (kx & 3) * 32]), acc);
                }
                af[h] = acc;
            }
            // x1 = x + att_feat; LN1 (warp-local)
            float xv[4], s1 = 0.f, sq = 0.f;
#pragma unroll
            for (int h = 0; h < 4; h++) {
                xv[h] = x1f[p * 128 + h * 32 + lane] + af[h];
                s1 += xv[h]; sq = fmaf(xv[h], xv[h], sq);
            }
#pragma unroll
            for (int o = 16; o; o >>= 1) {
                s1 += __shfl_xor_sync(0xffffffffu, s1, o);
                sq += __shfl_xor_sync(0xffffffffu, sq, o);
            }
            float mean = s1 * (1.f / 128.f);
            float inv = rsqrtf(sq * (1.f / 128.f) - mean * mean + 1e-5f);
#pragma unroll
            for (int h = 0; h < 4; h++) {
                int c = h * 32 + lane;
                float o = (xv[h] - mean) * inv * g1[c] + b1[c];
                x1f[p * 128 + c] = o;
                x1h[p * SLH + c] = __float2half(o);
            }
        }
        __syncthreads();   // A: epilogue done (kv free), gemm done (nf free), x1h ready

        // ======== PHASE Y ========
        if (h1) store_kv(sm, aK, aV, kb, vb, w8, gid, tig);
        float4 pfB[8];
        if (h2) {
            unsigned* nfU = (unsigned*)(sm + OFF_NF);
#pragma unroll
            for (int k = 0; k < 8; k++) {
                int r = k * 8 + r5;
                int sw = ((r >> 2) & 1) * 4;
                half2* d = (half2*)(nfU + r * SNU + ((c4t * 2) ^ sw));
                d[0] = __floats2half2_rn(pfA[k].x, pfA[k].y);
                d[1] = __floats2half2_rn(pfA[k].z, pfA[k].w);
            }
            if (tid < 128) {
                half* nf = (half*)(sm + OFF_NF);
                int swh = ((tid >> 2) & 1) * 8;
                nf[tid * SNH + (128 ^ swh)] = __float2half(xz0);
                nf[tid * SNH + (129 ^ swh)] = __float2half(xz1);
                nf[tid * SNH + (130 ^ swh)] = __float2half(xz2);
            }
#pragma unroll
            for (int k = 0; k < 8; k++) {
                int src = min(nb2 * 128 + 64 + k * 8 + r5, n16 - 1);
                pfB[k] = ((const float4*)knn)[src * 32 + c4t];
            }
        }
        // lin mma: warp w8 -> cols w8*16..+15 (rows 8..15 implicit zero)
        {
            int c0 = w8 * 16;
            float acc[2][4];
#pragma unroll
            for (int i = 0; i < 2; i++)
#pragma unroll
                for (int l = 0; l < 4; l++) acc[i][l] = 0.f;
            for (int ch = 0; ch < 8; ch++) {
                int kc = ch * 8 + tig;
                const unsigned* p0 = (const unsigned*)(sm + OFF_X1H) + gid * SLU;
                unsigned a[4] = {p0[kc], 0u, p0[kc + 4], 0u};
#pragma unroll
                for (int nt = 0; nt < 2; nt++) {
                    const unsigned* pb = (const unsigned*)(sm + OFF_WL) + (c0 + nt * 8 + gid) * SLU;
                    mma16816(acc[nt], a, pb[kc], pb[kc + 4]);
                }
            }
#pragma unroll
            for (int nt = 0; nt < 2; nt++) {
                int c = c0 + nt * 8 + 2 * tig;
                yb[gid * 128 + c]     = acc[nt][0];
                yb[gid * 128 + c + 1] = acc[nt][1];
            }
        }
        __syncthreads();   // B: yb written
#pragma unroll
        for (int kq = 0; kq < 4; kq++) {
            int i = tid + kq * 256;
            yb[i] += x1f[i] + lb[i & 127];
        }
        __syncthreads();   // D: combine done
        // LN2 + store: warp w8 owns row w8
        {
            layernorm_row(yb + w8 * 128, g2, b2, lane);
            int np = blk * 8 + w8;
            if (np < n)
                ((float4*)(out + (size_t)np * 128))[lane] = ((float4*)(yb + w8 * 128))[lane];
        }
        if (h1) {   // stage next Q/x (qoY consumed in phase X; x1f consumed at combine)
            ((float4*)qoY)[tid] = pq;
            ((float4*)x1f)[tid] = px;
        }
        if (h2) {   // drain pfB -> nf rows 64..127
            unsigned* nfU = (unsigned*)(sm + OFF_NF);
#pragma unroll
            for (int k = 0; k < 8; k++) {
                int r = 64 + k * 8 + r5;
                int sw = ((r >> 2) & 1) * 4;
                half2* d = (half2*)(nfU + r * SNU + ((c4t * 2) ^ sw));
                d[0] = __floats2half2_rn(pfB[k].x, pfB[k].y);
                d[1] = __floats2half2_rn(pfB[k].z, pfB[k].w);
            }
        }
        __syncthreads();   // C: iteration boundary
    }
}

extern "C" void kernel_launch(void* const* d_in, const int* in_sizes, int n_in,
                              void* d_out, int out_size) {
    const float* x    = (const float*)d_in[0];
    const float* knn  = (const float*)d_in[1];
    const float* xyz  = (const float*)d_in[2];
    const float* q_w  = (const float*)d_in[3];
    const float* q_b  = (const float*)d_in[4];
    const float* k_w  = (const float*)d_in[5];
    const float* k_b  = (const float*)d_in[6];
    const float* v_w  = (const float*)d_in[7];
    const float* v_b  = (const float*)d_in[8];
    const float* lw   = (const float*)d_in[9];
    const float* lb   = (const float*)d_in[10];
    const float* l1g  = (const float*)d_in[11];
    const float* l1b  = (const float*)d_in[12];
    const float* l2g  = (const float*)d_in[13];
    const float* l2b  = (const float*)d_in[14];
    float* out = (float*)d_out;
    int n = in_sizes[0] / 128;

    int smem1 = (2 * 128 * LQ) * 2 + 128 * 4;
    cudaFuncSetAttribute(qo_kernel, cudaFuncAttributeMaxDynamicSharedMemorySize, smem1);
    cudaFuncSetAttribute(tb_main,  cudaFuncAttributeMaxDynamicSharedMemorySize, SMEM_TOT);
    int nsm = 148;
    cudaDeviceGetAttribute(&nsm, cudaDevAttrMultiProcessorCount, 0);

    qo_kernel<<<(n + 127) / 128, 256, smem1>>>(x, q_w, q_b, n);
    tb_main<<<nsm, 256, SMEM_TOT>>>(x, knn, xyz, k_w, k_b, v_w, v_b,
                                    lw, lb, l1g, l1b, l2g, l2b, out, n);
}

// round 13
// speedup vs baseline: 1.0943x; 1.0943x over previous
#include <cuda_runtime.h>
#include <cuda_fp16.h>
#include <cstdint>

#define LQ 152        // qo_kernel smem stride (halves)
#define SNU 72        // nf/wt_k/wt_v u32 stride (144 halves), XOR-4 swizzled
#define SNH 144
#define SLU 66        // wt_l/x1h u32 stride (132 halves)
#define SLH 132

// smem byte offsets
#define OFF_WK  0
#define OFF_WV  36864
#define OFF_NF  73728          // 2 x 36864
#define OFF_WL  147456         // 33792
#define OFF_X1H 181248         // 2112
#define OFF_QO  183360         // 4096
#define OFF_X1F 187456         // 4096
#define OFF_YB  191552         // 4096
#define OFF_CB  195648         // 4096
#define SMEM_TOT 199744

__device__ float g_QO[(size_t)100000 * 128];

__device__ __forceinline__ void mma16816(float* d, const unsigned* a, unsigned b0, unsigned b1) {
    asm volatile(
        "mma.sync.aligned.m16n8k16.row.col.f32.f16.f16.f32 "
        "{%0,%1,%2,%3}, {%4,%5,%6,%7}, {%8,%9}, {%0,%1,%2,%3};\n"
        : "+f"(d[0]), "+f"(d[1]), "+f"(d[2]), "+f"(d[3])
        : "r"(a[0]), "r"(a[1]), "r"(a[2]), "r"(a[3]), "r"(b0), "r"(b1));
}

// warp w: rows w*16..+15 (128 cols) of BOTH K and V projections, acc in regs.
__device__ __forceinline__ void gemm_regs(const char* sm, const char* nfBase,
                                          float (&aK)[16][4], float (&aV)[16][4],
                                          int w8, int gid, int tig) {
    const unsigned* nfU = (const unsigned*)nfBase;
    const unsigned* wkU = (const unsigned*)(sm + OFF_WK);
    const unsigned* wvU = (const unsigned*)(sm + OFF_WV);
    int sw = ((gid >> 2) & 1) * 4;
#pragma unroll
    for (int i = 0; i < 16; i++)
#pragma unroll
        for (int l = 0; l < 4; l++) { aK[i][l] = 0.f; aV[i][l] = 0.f; }
    for (int ch = 0; ch < 9; ch++) {
        int kr = ch * 8 + tig;
        int kc = kr ^ sw, kc4 = (kr + 4) ^ sw;
        const unsigned* p0 = nfU + (w8 * 16 + gid) * SNU;
        const unsigned* p1 = p0 + 8 * SNU;
        unsigned A[4] = {p0[kc], p1[kc], p0[kc4], p1[kc4]};
#pragma unroll
        for (int nt = 0; nt < 16; nt++) {
            const unsigned* pk = wkU + (nt * 8 + gid) * SNU;
            mma16816(aK[nt], A, pk[kc], pk[kc4]);
            const unsigned* pv = wvU + (nt * 8 + gid) * SNU;
            mma16816(aV[nt], A, pv[kc], pv[kc4]);
        }
    }
}

// direct LDG->STS nf loader (prologue); writes bias-one at col 131
__device__ __forceinline__ void load_nf_direct(char* nfBase, const float* knn, const float* xyz,
                                               int blk, int n16, int tid) {
    unsigned* nfU = (unsigned*)nfBase;
    for (int i4 = tid; i4 < 4096; i4 += 256) {
        int r = i4 >> 5, c4 = i4 & 31;
        int src = min(blk * 128 + r, n16 - 1);
        float4 v = ((const float4*)knn)[src * 32 + c4];
        int sw = ((r >> 2) & 1) * 4;
        half2* d = (half2*)(nfU + r * SNU + ((c4 * 2) ^ sw));
        d[0] = __floats2half2_rn(v.x, v.y);
        d[1] = __floats2half2_rn(v.z, v.w);
    }
    if (tid < 128) {
        half* nf = (half*)nfBase;
        int src = min(blk * 128 + tid, n16 - 1);
        int swh = ((tid >> 2) & 1) * 8;
        nf[tid * SNH + (128 ^ swh)] = __float2half(xyz[src * 3 + 0]);
        nf[tid * SNH + (129 ^ swh)] = __float2half(xyz[src * 3 + 1]);
        nf[tid * SNH + (130 ^ swh)] = __float2half(xyz[src * 3 + 2]);
        nf[tid * SNH + (131 ^ swh)] = __float2half(1.0f);
    }
}

// one warp normalizes one 128-float smem row in place
__device__ __forceinline__ void layernorm_row(float* v, const float* g, const float* b, int lane) {
    float4 val = ((float4*)v)[lane];
    float s = val.x + val.y + val.z + val.w;
    float s2 = val.x * val.x + val.y * val.y + val.z * val.z + val.w * val.w;
#pragma unroll
    for (int o = 16; o; o >>= 1) {
        s  += __shfl_xor_sync(0xffffffffu, s, o);
        s2 += __shfl_xor_sync(0xffffffffu, s2, o);
    }
    float m = s * (1.f / 128.f);
    float inv = rsqrtf(s2 * (1.f / 128.f) - m * m + 1e-5f);
    int c = lane * 4;
    float o0 = (val.x - m) * inv * g[c] + b[c];
    float o1 = (val.y - m) * inv * g[c + 1] + b[c + 1];
    float o2 = (val.z - m) * inv * g[c + 2] + b[c + 2];
    float o3 = (val.w - m) * inv * g[c + 3] + b[c + 3];
    ((float4*)v)[lane] = make_float4(o0, o1, o2, o3);
}

// ---------------- Kernel 1: QO = x @ q_w + q_b ----------------
__global__ void __launch_bounds__(256)
qo_kernel(const float* __restrict__ x, const float* __restrict__ q_w,
          const float* __restrict__ q_b, int n) {
    extern __shared__ char smraw[];
    half* xs = (half*)smraw;
    half* wt = xs + 128 * LQ;
    float* qb = (float*)(wt + 128 * LQ);
    int tid = threadIdx.x;
    int base = blockIdx.x * 128;
    {
        half2 z = __floats2half2_rn(0.f, 0.f);
        half2* p = (half2*)smraw;
        for (int i = tid; i < 128 * LQ; i += 256) p[i] = z;
    }
    __syncthreads();
    for (int i = tid; i < 128 * 128; i += 256) {
        int j = i >> 7, c = i & 127;
        wt[c * LQ + j] = __float2half(q_w[i]);
    }
    for (int i4 = tid; i4 < 4096; i4 += 256) {
        int r = i4 >> 5, c4 = i4 & 31;
        int src = min(base + r, n - 1);
        float4 v = ((const float4*)x)[src * 32 + c4];
        half2* d = (half2*)(xs + r * LQ + c4 * 4);
        d[0] = __floats2half2_rn(v.x, v.y);
        d[1] = __floats2half2_rn(v.z, v.w);
    }
    if (tid < 128) qb[tid] = q_b[tid];
    __syncthreads();

    int w = tid >> 5, lane = tid & 31, gid = lane >> 2, tig = lane & 3;
    int r0 = (w & 3) * 32, c0 = (w >> 2) * 64;
    float acc[2][8][4];
#pragma unroll
    for (int i = 0; i < 2; i++)
#pragma unroll
        for (int j = 0; j < 8; j++)
#pragma unroll
            for (int l = 0; l < 4; l++) acc[i][j][l] = 0.f;
    for (int ch = 0; ch < 8; ch++) {
        int kc = ch * 8 + tig;
        unsigned a[2][4];
#pragma unroll
        for (int mt = 0; mt < 2; mt++) {
            const unsigned* p0 = (const unsigned*)(xs + (r0 + mt * 16 + gid) * LQ);
            const unsigned* p1 = (const unsigned*)(xs + (r0 + mt * 16 + gid + 8) * LQ);
            a[mt][0] = p0[kc];     a[mt][1] = p1[kc];
            a[mt][2] = p0[kc + 4]; a[mt][3] = p1[kc + 4];
        }
#pragma unroll
        for (int nt = 0; nt < 8; nt++) {
            const unsigned* pb = (const unsigned*)(wt + (c0 + nt * 8 + gid) * LQ);
            unsigned b0 = pb[kc], b1 = pb[kc + 4];
            mma16816(acc[0][nt], a[0], b0, b1);
            mma16816(acc[1][nt], a[1], b0, b1);
        }
    }
#pragma unroll
    for (int mt = 0; mt < 2; mt++)
#pragma unroll
        for (int nt = 0; nt < 8; nt++) {
            int r = r0 + mt * 16 + gid, c = c0 + nt * 8 + 2 * tig;
            float* d = acc[mt][nt];
            if (base + r < n) {
                g_QO[(size_t)(base + r) * 128 + c]     = d[0] + qb[c];
                g_QO[(size_t)(base + r) * 128 + c + 1] = d[1] + qb[c + 1];
            }
            if (base + r + 8 < n) {
                g_QO[(size_t)(base + r + 8) * 128 + c]     = d[2] + qb[c];
                g_QO[(size_t)(base + r + 8) * 128 + c + 1] = d[3] + qb[c + 1];
            }
        }
}

// ---------------- Kernel 2: K/V in registers, register epilogue ----------------
__global__ void __launch_bounds__(256, 1)
tb_main(const float* __restrict__ x,
        const float* __restrict__ knn, const float* __restrict__ xyz,
        const float* __restrict__ k_w, const float* __restrict__ k_b,
        const float* __restrict__ v_w, const float* __restrict__ v_b,
        const float* __restrict__ lin_w, const float* __restrict__ lin_b,
        const float* __restrict__ l1g, const float* __restrict__ l1b,
        const float* __restrict__ l2g, const float* __restrict__ l2b,
        float* __restrict__ out, int n)
{
    extern __shared__ __align__(16) char sm[];
    int tid = threadIdx.x;
    int w8 = tid >> 5, lane = tid & 31, gid = lane >> 2, tig = lane & 3;
    float* qoY = (float*)(sm + OFF_QO);
    float* x1f = (float*)(sm + OFF_X1F);
    float* yb  = (float*)(sm + OFF_YB);
    float* cb  = (float*)(sm + OFF_CB);
    half*  x1h = (half*)(sm + OFF_X1H);

    // zero wt_k/wt_v/nf(both buffers): padding cols must stay 0
    {
        float4 z4 = make_float4(0.f, 0.f, 0.f, 0.f);
        for (int i = tid; i < 147456 / 16; i += 256) ((float4*)sm)[i] = z4;
    }
    __syncthreads();
    // weights transposed; K/V bias folded as weight row 131 (nf col 131 == 1.0)
    for (int i = tid; i < 132 * 128; i += 256) {
        int j = i >> 7, c = i & 127;
        int swh = ((c >> 2) & 1) * 8;
        float fk = (j < 131) ? k_w[j * 128 + c] : k_b[c];
        float fv = (j < 131) ? v_w[j * 128 + c] : v_b[c];
        ((half*)(sm + OFF_WK))[c * SNH + (j ^ swh)] = __float2half(fk);
        ((half*)(sm + OFF_WV))[c * SNH + (j ^ swh)] = __float2half(fv);
        if (j < 128) ((half*)(sm + OFF_WL))[c * SLH + j] = __float2half(lin_w[i]);
    }
    if (tid < 128) {
        cb[tid]       = lin_b[tid]; cb[128 + tid] = l1g[tid];
        cb[256 + tid] = l1b[tid];   cb[384 + tid] = l2g[tid];
        cb[512 + tid] = l2b[tid];
    }
    const float *lb = cb, *g1 = cb + 128, *b1 = cb + 256, *g2 = cb + 384, *b2 = cb + 512;

    int nblk = (n + 7) >> 3;
    int n16 = n * 16;
    int G = gridDim.x;
    int blk0 = blockIdx.x;
    if (blk0 >= nblk) return;

    // ---- prologue: nf(b0)->buf0, stage Q/x(b0) ----
    load_nf_direct(sm + OFF_NF, knn, xyz, blk0, n16, tid);
    {
        int np = min(blk0 * 8 + w8, n - 1);
        ((float4*)qoY)[tid] = ((const float4*)g_QO)[np * 32 + lane];
        ((float4*)x1f)[tid] = ((const float4*)x)[np * 32 + lane];
    }
    __syncthreads();

    float aK[16][4], aV[16][4];
    int buf = 0;
    const float inv_d = 0.08838834764831845f;  // 1/sqrt(128)

    for (int blk = blk0; blk < nblk; blk += G) {
        int nb1 = blk + G;
        bool h1 = nb1 < nblk;
        char* nfCur = sm + OFF_NF + buf * 36864;
        char* nfNxt = sm + OFF_NF + (buf ^ 1) * 36864;

        // ======== PHASE X ========
        // prefetch batch A (next rows 0..63) before gemm
        float4 pfA[8];
        if (h1) {
#pragma unroll
            for (int k = 0; k < 8; k++) {
                int src = min(nb1 * 128 + k * 8 + w8, n16 - 1);
                pfA[k] = ((const float4*)knn)[src * 32 + lane];
            }
        }

        gemm_regs(sm, nfCur, aK, aV, w8, gid, tig);

        // drain A -> nf[buf^1]; issue batch B + xyz
        float4 pfB[8];
        float xz0 = 0.f, xz1 = 0.f, xz2 = 0.f;
        if (h1) {
            unsigned* nfU = (unsigned*)nfNxt;
#pragma unroll
            for (int k = 0; k < 8; k++) {
                int r = k * 8 + w8;
                int sw = ((r >> 2) & 1) * 4;
                half2* d = (half2*)(nfU + r * SNU + ((lane * 2) ^ sw));
                d[0] = __floats2half2_rn(pfA[k].x, pfA[k].y);
                d[1] = __floats2half2_rn(pfA[k].z, pfA[k].w);
            }
#pragma unroll
            for (int k = 0; k < 8; k++) {
                int src = min(nb1 * 128 + 64 + k * 8 + w8, n16 - 1);
                pfB[k] = ((const float4*)knn)[src * 32 + lane];
            }
            if (tid < 128) {
                int src = min(nb1 * 128 + tid, n16 - 1);
                xz0 = xyz[src * 3 + 0]; xz1 = xyz[src * 3 + 1]; xz2 = xyz[src * 3 + 2];
            }
        }

        // ---- register epilogue: warp w8 = point w8 ----
        {
            int h0 = gid >> 2;                    // 0 or 1
            const float* qrow = qoY + w8 * 128;
            const float* xrow = x1f + w8 * 128;
            float qv[2][4][2];
#pragma unroll
            for (int m = 0; m < 2; m++) {
                int h = h0 + 2 * m;
#pragma unroll
                for (int q3 = 0; q3 < 4; q3++) {
                    qv[m][q3][0] = qrow[h * 32 + q3 * 8 + 2 * tig];
                    qv[m][q3][1] = qrow[h * 32 + q3 * 8 + 2 * tig + 1];
                }
            }
            // att raw partials
            float S[2][4];
#pragma unroll
            for (int m = 0; m < 2; m++)
#pragma unroll
                for (int j = 0; j < 4; j++) S[m][j] = 0.f;
#pragma unroll
            for (int nt = 0; nt < 16; nt++) {
                int j = nt >> 2, q3 = nt & 3;
                S[0][j] = fmaf(aK[nt][0], qv[0][q3][0], fmaf(aK[nt][1], qv[0][q3][1], S[0][j]));
                S[1][j] = fmaf(aK[nt][2], qv[1][q3][0], fmaf(aK[nt][3], qv[1][q3][1], S[1][j]));
            }
#pragma unroll
            for (int m = 0; m < 2; m++)
#pragma unroll
                for (int j = 0; j < 4; j++) {
                    S[m][j] += __shfl_xor_sync(0xffffffffu, S[m][j], 1);
                    S[m][j] += __shfl_xor_sync(0xffffffffu, S[m][j], 2);
                }
            // softmax per head (over kk = (gid&3)*4 + j)
            float a_[2][4];
#pragma unroll
            for (int m = 0; m < 2; m++) {
                float mx = fmaxf(fmaxf(S[m][0], S[m][1]), fmaxf(S[m][2], S[m][3]));
                mx = fmaxf(mx, __shfl_xor_sync(0xffffffffu, mx, 4));
                mx = fmaxf(mx, __shfl_xor_sync(0xffffffffu, mx, 8));
                float e0 = __expf((S[m][0] - mx) * inv_d);
                float e1 = __expf((S[m][1] - mx) * inv_d);
                float e2 = __expf((S[m][2] - mx) * inv_d);
                float e3 = __expf((S[m][3] - mx) * inv_d);
                float sl = e0 + e1 + e2 + e3;
                sl += __shfl_xor_sync(0xffffffffu, sl, 4);
                sl += __shfl_xor_sync(0xffffffffu, sl, 8);
                float r = 1.f / sl;
                a_[m][0] = e0 * r; a_[m][1] = e1 * r; a_[m][2] = e2 * r; a_[m][3] = e3 * r;
            }
            // att_feat partials
            float F[2][4][2];
#pragma unroll
            for (int m = 0; m < 2; m++)
#pragma unroll
                for (int q3 = 0; q3 < 4; q3++) { F[m][q3][0] = 0.f; F[m][q3][1] = 0.f; }
#pragma unroll
            for (int nt = 0; nt < 16; nt++) {
                int j = nt >> 2, q3 = nt & 3;
                F[0][q3][0] = fmaf(a_[0][j], aV[nt][0], F[0][q3][0]);
                F[0][q3][1] = fmaf(a_[0][j], aV[nt][1], F[0][q3][1]);
                F[1][q3][0] = fmaf(a_[1][j], aV[nt][2], F[1][q3][0]);
                F[1][q3][1] = fmaf(a_[1][j], aV[nt][3], F[1][q3][1]);
            }
#pragma unroll
            for (int m = 0; m < 2; m++)
#pragma unroll
                for (int q3 = 0; q3 < 4; q3++)
#pragma unroll
                    for (int b = 0; b < 2; b++) {
                        F[m][q3][b] += __shfl_xor_sync(0xffffffffu, F[m][q3][b], 4);
                        F[m][q3][b] += __shfl_xor_sync(0xffffffffu, F[m][q3][b], 8);
                    }
            // x1 = x + att_feat; LN1 stats (values replicated 4x over gid&3)
            float xv[2][4][2], s1 = 0.f, sq = 0.f;
#pragma unroll
            for (int m = 0; m < 2; m++) {
                int h = h0 + 2 * m;
#pragma unroll
                for (int q3 = 0; q3 < 4; q3++)
#pragma unroll
                    for (int b = 0; b < 2; b++) {
                        float v = xrow[h * 32 + q3 * 8 + 2 * tig + b] + F[m][q3][b];
                        xv[m][q3][b] = v;
                        s1 += v; sq = fmaf(v, v, sq);
                    }
            }
#pragma unroll
            for (int o = 16; o; o >>= 1) {
                s1 += __shfl_xor_sync(0xffffffffu, s1, o);
                sq += __shfl_xor_sync(0xffffffffu, sq, o);
            }
            float mean = s1 * (1.f / 512.f);
            float inv = rsqrtf(sq * (1.f / 512.f) - mean * mean + 1e-5f);
            if ((gid & 3) == 0) {
#pragma unroll
                for (int m = 0; m < 2; m++) {
                    int h = h0 + 2 * m;
#pragma unroll
                    for (int q3 = 0; q3 < 4; q3++) {
                        int c = h * 32 + q3 * 8 + 2 * tig;
                        float o0 = (xv[m][q3][0] - mean) * inv * g1[c] + b1[c];
                        float o1 = (xv[m][q3][1] - mean) * inv * g1[c + 1] + b1[c + 1];
                        *(float2*)(x1f + w8 * 128 + c) = make_float2(o0, o1);
                        *(half2*)(x1h + w8 * SLH + c) = __floats2half2_rn(o0, o1);
                    }
                }
            }
        }
        __syncthreads();   // A: x1h/x1f(LN1) ready; nf[buf^1] rows 0..63 drained

        // ======== PHASE Y ========
        // lin mma: warp w8 -> cols w8*16..+15 (rows 8..15 implicit zero)
        {
            int c0 = w8 * 16;
            float acc[2][4];
#pragma unroll
            for (int i = 0; i < 2; i++)
#pragma unroll
                for (int l = 0; l < 4; l++) acc[i][l] = 0.f;
            for (int ch = 0; ch < 8; ch++) {
                int kc = ch * 8 + tig;
                const unsigned* p0 = (const unsigned*)(sm + OFF_X1H) + gid * SLU;
                unsigned a[4] = {p0[kc], 0u, p0[kc + 4], 0u};
#pragma unroll
                for (int nt = 0; nt < 2; nt++) {
                    const unsigned* pb = (const unsigned*)(sm + OFF_WL) + (c0 + nt * 8 + gid) * SLU;
                    mma16816(acc[nt], a, pb[kc], pb[kc + 4]);
                }
            }
#pragma unroll
            for (int nt = 0; nt < 2; nt++) {
                int c = c0 + nt * 8 + 2 * tig;
                yb[gid * 128 + c]     = acc[nt][0];
                yb[gid * 128 + c + 1] = acc[nt][1];
            }
        }
        // drain batch B + xyz -> nf[buf^1]
        if (h1) {
            unsigned* nfU = (unsigned*)nfNxt;
#pragma unroll
            for (int k = 0; k < 8; k++) {
                int r = 64 + k * 8 + w8;
                int sw = ((r >> 2) & 1) * 4;
                half2* d = (half2*)(nfU + r * SNU + ((lane * 2) ^ sw));
                d[0] = __floats2half2_rn(pfB[k].x, pfB[k].y);
                d[1] = __floats2half2_rn(pfB[k].z, pfB[k].w);
            }
            if (tid < 128) {
                half* nf = (half*)nfNxt;
                int swh = ((tid >> 2) & 1) * 8;
                nf[tid * SNH + (128 ^ swh)] = __float2half(xz0);
                nf[tid * SNH + (129 ^ swh)] = __float2half(xz1);
                nf[tid * SNH + (130 ^ swh)] = __float2half(xz2);
                nf[tid * SNH + (131 ^ swh)] = __float2half(1.0f);
            }
        }
        __syncthreads();   // B: yb ready
#pragma unroll
        for (int kq = 0; kq < 4; kq++) {
            int i = tid + kq * 256;
            yb[i] += x1f[i] + lb[i & 127];
        }
        __syncthreads();   // D: combine done
        // LN2 + store: warp w8 owns row w8
        layernorm_row(yb + w8 * 128, g2, b2, lane);
        {
            int np = blk * 8 + w8;
            if (np < n)
                ((float4*)(out + (size_t)np * 128))[lane] = ((float4*)(yb + w8 * 128))[lane];
        }
        // stage next Q/x (per-warp row, no cross-warp hazard)
        if (h1) {
            int np = min(nb1 * 8 + w8, n - 1);
            ((float4*)qoY)[tid] = ((const float4*)g_QO)[np * 32 + lane];
            ((float4*)x1f)[tid] = ((const float4*)x)[np * 32 + lane];
        }
        __syncthreads();   // C: iteration boundary
        buf ^= 1;
    }
}

extern "C" void kernel_launch(void* const* d_in, const int* in_sizes, int n_in,
                              void* d_out, int out_size) {
    const float* x    = (const float*)d_in[0];
    const float* knn  = (const float*)d_in[1];
    const float* xyz  = (const float*)d_in[2];
    const float* q_w  = (const float*)d_in[3];
    const float* q_b  = (const float*)d_in[4];
    const float* k_w  = (const float*)d_in[5];
    const float* k_b  = (const float*)d_in[6];
    const float* v_w  = (const float*)d_in[7];
    const float* v_b  = (const float*)d_in[8];
    const float* lw   = (const float*)d_in[9];
    const float* lb   = (const float*)d_in[10];
    const float* l1g  = (const float*)d_in[11];
    const float* l1b  = (const float*)d_in[12];
    const float* l2g  = (const float*)d_in[13];
    const float* l2b  = (const float*)d_in[14];
    float* out = (float*)d_out;
    int n = in_sizes[0] / 128;

    int smem1 = (2 * 128 * LQ) * 2 + 128 * 4;
    cudaFuncSetAttribute(qo_kernel, cudaFuncAttributeMaxDynamicSharedMemorySize, smem1);
    cudaFuncSetAttribute(tb_main,  cudaFuncAttributeMaxDynamicSharedMemorySize, SMEM_TOT);
    int nsm = 148;
    cudaDeviceGetAttribute(&nsm, cudaDevAttrMultiProcessorCount, 0);

    qo_kernel<<<(n + 127) / 128, 256, smem1>>>(x, q_w, q_b, n);
    tb_main<<<nsm, 256, SMEM_TOT>>>(x, knn, xyz, k_w, k_b, v_w, v_b,
                                    lw, lb, l1g, l1b, l2g, l2b, out, n);
}

// round 14
// speedup vs baseline: 1.2136x; 1.1090x over previous
#include <cuda_runtime.h>
#include <cuda_fp16.h>
#include <cstdint>

#define SNU 72        // nf/wt_k/wt_v u32 stride (144 halves), XOR-4 swizzled
#define SNH 144
#define SLU 66        // wt_l/wt_q/x1h u32 stride (132 halves)
#define SLH 132

// smem byte offsets
#define OFF_WK  0              // 36864
#define OFF_WV  36864          // 36864
#define OFF_NF  73728          // 2 x 36864
#define OFF_WL  147456         // 33792
#define OFF_WQ  181248         // 33792
#define OFF_X1H 215040         // 2112  (x8h / x1h overlay)
#define OFF_QO  217152         // 4096  (Q fp32; yb overlay)
#define OFF_X1F 221248         // 4096
#define OFF_CB  225344         // 3072
#define SMEM_TOT 228416

__device__ __forceinline__ void mma16816(float* d, const unsigned* a, unsigned b0, unsigned b1) {
    asm volatile(
        "mma.sync.aligned.m16n8k16.row.col.f32.f16.f16.f32 "
        "{%0,%1,%2,%3}, {%4,%5,%6,%7}, {%8,%9}, {%0,%1,%2,%3};\n"
        : "+f"(d[0]), "+f"(d[1]), "+f"(d[2]), "+f"(d[3])
        : "r"(a[0]), "r"(a[1]), "r"(a[2]), "r"(a[3]), "r"(b0), "r"(b1));
}

// warp w: rows w*16..+15 (128 cols) of BOTH K and V projections, acc in regs.
__device__ __forceinline__ void gemm_regs(const char* sm, const char* nfBase,
                                          float (&aK)[16][4], float (&aV)[16][4],
                                          int w8, int gid, int tig) {
    const unsigned* nfU = (const unsigned*)nfBase;
    const unsigned* wkU = (const unsigned*)(sm + OFF_WK);
    const unsigned* wvU = (const unsigned*)(sm + OFF_WV);
    int sw = ((gid >> 2) & 1) * 4;
#pragma unroll
    for (int i = 0; i < 16; i++)
#pragma unroll
        for (int l = 0; l < 4; l++) { aK[i][l] = 0.f; aV[i][l] = 0.f; }
    for (int ch = 0; ch < 9; ch++) {
        int kr = ch * 8 + tig;
        int kc = kr ^ sw, kc4 = (kr + 4) ^ sw;
        const unsigned* p0 = nfU + (w8 * 16 + gid) * SNU;
        const unsigned* p1 = p0 + 8 * SNU;
        unsigned A[4] = {p0[kc], p1[kc], p0[kc4], p1[kc4]};
#pragma unroll
        for (int nt = 0; nt < 16; nt++) {
            const unsigned* pk = wkU + (nt * 8 + gid) * SNU;
            mma16816(aK[nt], A, pk[kc], pk[kc4]);
            const unsigned* pv = wvU + (nt * 8 + gid) * SNU;
            mma16816(aV[nt], A, pv[kc], pv[kc4]);
        }
    }
}

// direct LDG->STS nf loader (prologue); writes bias-one at col 131
__device__ __forceinline__ void load_nf_direct(char* nfBase, const float* knn, const float* xyz,
                                               int blk, int n16, int tid) {
    unsigned* nfU = (unsigned*)nfBase;
    for (int i4 = tid; i4 < 4096; i4 += 256) {
        int r = i4 >> 5, c4 = i4 & 31;
        int src = min(blk * 128 + r, n16 - 1);
        float4 v = ((const float4*)knn)[src * 32 + c4];
        int sw = ((r >> 2) & 1) * 4;
        half2* d = (half2*)(nfU + r * SNU + ((c4 * 2) ^ sw));
        d[0] = __floats2half2_rn(v.x, v.y);
        d[1] = __floats2half2_rn(v.z, v.w);
    }
    if (tid < 128) {
        half* nf = (half*)nfBase;
        int src = min(blk * 128 + tid, n16 - 1);
        int swh = ((tid >> 2) & 1) * 8;
        nf[tid * SNH + (128 ^ swh)] = __float2half(xyz[src * 3 + 0]);
        nf[tid * SNH + (129 ^ swh)] = __float2half(xyz[src * 3 + 1]);
        nf[tid * SNH + (130 ^ swh)] = __float2half(xyz[src * 3 + 2]);
        nf[tid * SNH + (131 ^ swh)] = __float2half(1.0f);
    }
}

// one warp normalizes one 128-float smem row in place
__device__ __forceinline__ void layernorm_row(float* v, const float* g, const float* b, int lane) {
    float4 val = ((float4*)v)[lane];
    float s = val.x + val.y + val.z + val.w;
    float s2 = val.x * val.x + val.y * val.y + val.z * val.z + val.w * val.w;
#pragma unroll
    for (int o = 16; o; o >>= 1) {
        s  += __shfl_xor_sync(0xffffffffu, s, o);
        s2 += __shfl_xor_sync(0xffffffffu, s2, o);
    }
    float m = s * (1.f / 128.f);
    float inv = rsqrtf(s2 * (1.f / 128.f) - m * m + 1e-5f);
    int c = lane * 4;
    float o0 = (val.x - m) * inv * g[c] + b[c];
    float o1 = (val.y - m) * inv * g[c + 1] + b[c + 1];
    float o2 = (val.z - m) * inv * g[c + 2] + b[c + 2];
    float o3 = (val.w - m) * inv * g[c + 3] + b[c + 3];
    ((float4*)v)[lane] = make_float4(o0, o1, o2, o3);
}

__global__ void __launch_bounds__(256, 1)
tb_main(const float* __restrict__ x,
        const float* __restrict__ knn, const float* __restrict__ xyz,
        const float* __restrict__ q_w, const float* __restrict__ q_b,
        const float* __restrict__ k_w, const float* __restrict__ k_b,
        const float* __restrict__ v_w, const float* __restrict__ v_b,
        const float* __restrict__ lin_w, const float* __restrict__ lin_b,
        const float* __restrict__ l1g, const float* __restrict__ l1b,
        const float* __restrict__ l2g, const float* __restrict__ l2b,
        float* __restrict__ out, int n)
{
    extern __shared__ __align__(16) char sm[];
    int tid = threadIdx.x;
    int w8 = tid >> 5, lane = tid & 31, gid = lane >> 2, tig = lane & 3;
    float* qoY = (float*)(sm + OFF_QO);   // Q fp32; yb overlay
    float* yb  = (float*)(sm + OFF_QO);
    float* x1f = (float*)(sm + OFF_X1F);
    float* cb  = (float*)(sm + OFF_CB);
    half*  x1h = (half*)(sm + OFF_X1H);   // x8h / x1h overlay
    half*  x8h = (half*)(sm + OFF_X1H);

    // zero wt_k/wt_v/nf(both buffers): padding cols must stay 0
    {
        float4 z4 = make_float4(0.f, 0.f, 0.f, 0.f);
        for (int i = tid; i < 147456 / 16; i += 256) ((float4*)sm)[i] = z4;
    }
    __syncthreads();
    // weights transposed; K/V bias folded as weight row 131 (nf col 131 == 1.0)
    for (int i = tid; i < 132 * 128; i += 256) {
        int j = i >> 7, c = i & 127;
        int swh = ((c >> 2) & 1) * 8;
        float fk = (j < 131) ? k_w[j * 128 + c] : k_b[c];
        float fv = (j < 131) ? v_w[j * 128 + c] : v_b[c];
        ((half*)(sm + OFF_WK))[c * SNH + (j ^ swh)] = __float2half(fk);
        ((half*)(sm + OFF_WV))[c * SNH + (j ^ swh)] = __float2half(fv);
        if (j < 128) {
            ((half*)(sm + OFF_WL))[c * SLH + j] = __float2half(lin_w[i]);
            ((half*)(sm + OFF_WQ))[c * SLH + j] = __float2half(q_w[i]);
        }
    }
    if (tid < 128) {
        cb[tid]       = lin_b[tid]; cb[128 + tid] = l1g[tid];
        cb[256 + tid] = l1b[tid];   cb[384 + tid] = l2g[tid];
        cb[512 + tid] = l2b[tid];   cb[640 + tid] = q_b[tid];
    }
    const float *lb = cb, *g1 = cb + 128, *b1 = cb + 256;
    const float *g2 = cb + 384, *b2 = cb + 512, *qb = cb + 640;

    int nblk = (n + 7) >> 3;
    int n16 = n * 16;
    int G = gridDim.x;
    int blk0 = blockIdx.x;
    if (blk0 >= nblk) return;

    // ---- prologue: nf(b0)->buf0, stage x(b0) into x1f + x8h ----
    load_nf_direct(sm + OFF_NF, knn, xyz, blk0, n16, tid);
    {
        int np = min(blk0 * 8 + w8, n - 1);
        float4 v = ((const float4*)x)[np * 32 + lane];
        ((float4*)x1f)[tid] = v;
        half2* d = (half2*)(x8h + w8 * SLH + lane * 4);
        d[0] = __floats2half2_rn(v.x, v.y);
        d[1] = __floats2half2_rn(v.z, v.w);
    }
    __syncthreads();

    float aK[16][4], aV[16][4];
    int buf = 0;
    const float inv_d = 0.08838834764831845f;  // 1/sqrt(128)

    for (int blk = blk0; blk < nblk; blk += G) {
        int nb1 = blk + G;
        bool h1 = nb1 < nblk;
        char* nfCur = sm + OFF_NF + buf * 36864;
        char* nfNxt = sm + OFF_NF + (buf ^ 1) * 36864;

        // ======== PHASE X ========
        // early LDG issue: pfA (next nf rows 0..63) and next x
        float4 pfA[8], px;
        if (h1) {
#pragma unroll
            for (int k = 0; k < 8; k++) {
                int src = min(nb1 * 128 + k * 8 + w8, n16 - 1);
                pfA[k] = ((const float4*)knn)[src * 32 + lane];
            }
            int np = min(nb1 * 8 + w8, n - 1);
            px = ((const float4*)x)[np * 32 + lane];
        }

        // ---- Q gemm: warp w8 -> cols w8*16..+15, rows = points (gid) ----
        {
            int c0 = w8 * 16;
            float acc[2][4];
#pragma unroll
            for (int i = 0; i < 2; i++)
#pragma unroll
                for (int l = 0; l < 4; l++) acc[i][l] = 0.f;
            for (int ch = 0; ch < 8; ch++) {
                int kc = ch * 8 + tig;
                const unsigned* p0 = (const unsigned*)(sm + OFF_X1H) + gid * SLU;
                unsigned a[4] = {p0[kc], 0u, p0[kc + 4], 0u};
#pragma unroll
                for (int nt = 0; nt < 2; nt++) {
                    const unsigned* pb = (const unsigned*)(sm + OFF_WQ) + (c0 + nt * 8 + gid) * SLU;
                    mma16816(acc[nt], a, pb[kc], pb[kc + 4]);
                }
            }
#pragma unroll
            for (int nt = 0; nt < 2; nt++) {
                int c = c0 + nt * 8 + 2 * tig;
                qoY[gid * 128 + c]     = acc[nt][0] + qb[c];
                qoY[gid * 128 + c + 1] = acc[nt][1] + qb[c + 1];
            }
        }
        __syncthreads();   // Q: qoY ready

        gemm_regs(sm, nfCur, aK, aV, w8, gid, tig);

        // drain A -> nf[buf^1]; issue batch B + xyz
        float4 pfB[8];
        float xz0 = 0.f, xz1 = 0.f, xz2 = 0.f;
        if (h1) {
            unsigned* nfU = (unsigned*)nfNxt;
#pragma unroll
            for (int k = 0; k < 8; k++) {
                int r = k * 8 + w8;
                int sw = ((r >> 2) & 1) * 4;
                half2* d = (half2*)(nfU + r * SNU + ((lane * 2) ^ sw));
                d[0] = __floats2half2_rn(pfA[k].x, pfA[k].y);
                d[1] = __floats2half2_rn(pfA[k].z, pfA[k].w);
            }
#pragma unroll
            for (int k = 0; k < 8; k++) {
                int src = min(nb1 * 128 + 64 + k * 8 + w8, n16 - 1);
                pfB[k] = ((const float4*)knn)[src * 32 + lane];
            }
            if (tid < 128) {
                int src = min(nb1 * 128 + tid, n16 - 1);
                xz0 = xyz[src * 3 + 0]; xz1 = xyz[src * 3 + 1]; xz2 = xyz[src * 3 + 2];
            }
        }

        // ---- register epilogue: warp w8 = point w8 ----
        {
            int h0 = gid >> 2;                    // 0 or 1
            const float* qrow = qoY + w8 * 128;
            const float* xrow = x1f + w8 * 128;
            float qv[2][4][2];
#pragma unroll
            for (int m = 0; m < 2; m++) {
                int h = h0 + 2 * m;
#pragma unroll
                for (int q3 = 0; q3 < 4; q3++) {
                    qv[m][q3][0] = qrow[h * 32 + q3 * 8 + 2 * tig];
                    qv[m][q3][1] = qrow[h * 32 + q3 * 8 + 2 * tig + 1];
                }
            }
            // att raw partials
            float S[2][4];
#pragma unroll
            for (int m = 0; m < 2; m++)
#pragma unroll
                for (int j = 0; j < 4; j++) S[m][j] = 0.f;
#pragma unroll
            for (int nt = 0; nt < 16; nt++) {
                int j = nt >> 2, q3 = nt & 3;
                S[0][j] = fmaf(aK[nt][0], qv[0][q3][0], fmaf(aK[nt][1], qv[0][q3][1], S[0][j]));
                S[1][j] = fmaf(aK[nt][2], qv[1][q3][0], fmaf(aK[nt][3], qv[1][q3][1], S[1][j]));
            }
#pragma unroll
            for (int m = 0; m < 2; m++)
#pragma unroll
                for (int j = 0; j < 4; j++) {
                    S[m][j] += __shfl_xor_sync(0xffffffffu, S[m][j], 1);
                    S[m][j] += __shfl_xor_sync(0xffffffffu, S[m][j], 2);
                }
            // softmax per head (over kk = (gid&3)*4 + j)
            float a_[2][4];
#pragma unroll
            for (int m = 0; m < 2; m++) {
                float mx = fmaxf(fmaxf(S[m][0], S[m][1]), fmaxf(S[m][2], S[m][3]));
                mx = fmaxf(mx, __shfl_xor_sync(0xffffffffu, mx, 4));
                mx = fmaxf(mx, __shfl_xor_sync(0xffffffffu, mx, 8));
                float e0 = __expf((S[m][0] - mx) * inv_d);
                float e1 = __expf((S[m][1] - mx) * inv_d);
                float e2 = __expf((S[m][2] - mx) * inv_d);
                float e3 = __expf((S[m][3] - mx) * inv_d);
                float sl = e0 + e1 + e2 + e3;
                sl += __shfl_xor_sync(0xffffffffu, sl, 4);
                sl += __shfl_xor_sync(0xffffffffu, sl, 8);
                float r = 1.f / sl;
                a_[m][0] = e0 * r; a_[m][1] = e1 * r; a_[m][2] = e2 * r; a_[m][3] = e3 * r;
            }
            // att_feat partials
            float F[2][4][2];
#pragma unroll
            for (int m = 0; m < 2; m++)
#pragma unroll
                for (int q3 = 0; q3 < 4; q3++) { F[m][q3][0] = 0.f; F[m][q3][1] = 0.f; }
#pragma unroll
            for (int nt = 0; nt < 16; nt++) {
                int j = nt >> 2, q3 = nt & 3;
                F[0][q3][0] = fmaf(a_[0][j], aV[nt][0], F[0][q3][0]);
                F[0][q3][1] = fmaf(a_[0][j], aV[nt][1], F[0][q3][1]);
                F[1][q3][0] = fmaf(a_[1][j], aV[nt][2], F[1][q3][0]);
                F[1][q3][1] = fmaf(a_[1][j], aV[nt][3], F[1][q3][1]);
            }
#pragma unroll
            for (int m = 0; m < 2; m++)
#pragma unroll
                for (int q3 = 0; q3 < 4; q3++)
#pragma unroll
                    for (int b = 0; b < 2; b++) {
                        F[m][q3][b] += __shfl_xor_sync(0xffffffffu, F[m][q3][b], 4);
                        F[m][q3][b] += __shfl_xor_sync(0xffffffffu, F[m][q3][b], 8);
                    }
            // x1 = x + att_feat; LN1 stats (values replicated 4x over gid&3)
            float xv[2][4][2], s1 = 0.f, sq = 0.f;
#pragma unroll
            for (int m = 0; m < 2; m++) {
                int h = h0 + 2 * m;
#pragma unroll
                for (int q3 = 0; q3 < 4; q3++)
#pragma unroll
                    for (int b = 0; b < 2; b++) {
                        float v = xrow[h * 32 + q3 * 8 + 2 * tig + b] + F[m][q3][b];
                        xv[m][q3][b] = v;
                        s1 += v; sq = fmaf(v, v, sq);
                    }
            }
#pragma unroll
            for (int o = 16; o; o >>= 1) {
                s1 += __shfl_xor_sync(0xffffffffu, s1, o);
                sq += __shfl_xor_sync(0xffffffffu, sq, o);
            }
            float mean = s1 * (1.f / 512.f);
            float inv = rsqrtf(sq * (1.f / 512.f) - mean * mean + 1e-5f);
            if ((gid & 3) == 0) {
#pragma unroll
                for (int m = 0; m < 2; m++) {
                    int h = h0 + 2 * m;
#pragma unroll
                    for (int q3 = 0; q3 < 4; q3++) {
                        int c = h * 32 + q3 * 8 + 2 * tig;
                        float o0 = (xv[m][q3][0] - mean) * inv * g1[c] + b1[c];
                        float o1 = (xv[m][q3][1] - mean) * inv * g1[c + 1] + b1[c + 1];
                        *(float2*)(x1f + w8 * 128 + c) = make_float2(o0, o1);
                        *(half2*)(x1h + w8 * SLH + c) = __floats2half2_rn(o0, o1);
                    }
                }
            }
        }
        __syncthreads();   // A: x1h/x1f(LN1) ready; Q consumed (yb region free)

        // ======== PHASE Y ========
        // lin mma fused with combine: yb = lin(x1) + x1 + lin_b
        {
            int c0 = w8 * 16;
            float acc[2][4];
#pragma unroll
            for (int i = 0; i < 2; i++)
#pragma unroll
                for (int l = 0; l < 4; l++) acc[i][l] = 0.f;
            for (int ch = 0; ch < 8; ch++) {
                int kc = ch * 8 + tig;
                const unsigned* p0 = (const unsigned*)(sm + OFF_X1H) + gid * SLU;
                unsigned a[4] = {p0[kc], 0u, p0[kc + 4], 0u};
#pragma unroll
                for (int nt = 0; nt < 2; nt++) {
                    const unsigned* pb = (const unsigned*)(sm + OFF_WL) + (c0 + nt * 8 + gid) * SLU;
                    mma16816(acc[nt], a, pb[kc], pb[kc + 4]);
                }
            }
#pragma unroll
            for (int nt = 0; nt < 2; nt++) {
                int c = c0 + nt * 8 + 2 * tig;
                yb[gid * 128 + c]     = acc[nt][0] + x1f[gid * 128 + c]     + lb[c];
                yb[gid * 128 + c + 1] = acc[nt][1] + x1f[gid * 128 + c + 1] + lb[c + 1];
            }
        }
        // drain batch B + xyz -> nf[buf^1]
        if (h1) {
            unsigned* nfU = (unsigned*)nfNxt;
#pragma unroll
            for (int k = 0; k < 8; k++) {
                int r = 64 + k * 8 + w8;
                int sw = ((r >> 2) & 1) * 4;
                half2* d = (half2*)(nfU + r * SNU + ((lane * 2) ^ sw));
                d[0] = __floats2half2_rn(pfB[k].x, pfB[k].y);
                d[1] = __floats2half2_rn(pfB[k].z, pfB[k].w);
            }
            if (tid < 128) {
                half* nf = (half*)nfNxt;
                int swh = ((tid >> 2) & 1) * 8;
                nf[tid * SNH + (128 ^ swh)] = __float2half(xz0);
                nf[tid * SNH + (129 ^ swh)] = __float2half(xz1);
                nf[tid * SNH + (130 ^ swh)] = __float2half(xz2);
                nf[tid * SNH + (131 ^ swh)] = __float2half(1.0f);
            }
        }
        __syncthreads();   // B: yb ready
        // LN2 + store: warp w8 owns row w8
        layernorm_row(yb + w8 * 128, g2, b2, lane);
        {
            int np = blk * 8 + w8;
            if (np < n)
                ((float4*)(out + (size_t)np * 128))[lane] = ((float4*)(yb + w8 * 128))[lane];
        }
        // drain next x -> x1f + x8h (per-warp row; read next iter after barrier C)
        if (h1) {
            ((float4*)x1f)[tid] = px;
            half2* d = (half2*)(x8h + w8 * SLH + lane * 4);
            d[0] = __floats2half2_rn(px.x, px.y);
            d[1] = __floats2half2_rn(px.z, px.w);
        }
        __syncthreads();   // C: iteration boundary
        buf ^= 1;
    }
}

extern "C" void kernel_launch(void* const* d_in, const int* in_sizes, int n_in,
                              void* d_out, int out_size) {
    const float* x    = (const float*)d_in[0];
    const float* knn  = (const float*)d_in[1];
    const float* xyz  = (const float*)d_in[2];
    const float* q_w  = (const float*)d_in[3];
    const float* q_b  = (const float*)d_in[4];
    const float* k_w  = (const float*)d_in[5];
    const float* k_b  = (const float*)d_in[6];
    const float* v_w  = (const float*)d_in[7];
    const float* v_b  = (const float*)d_in[8];
    const float* lw   = (const float*)d_in[9];
    const float* lb   = (const float*)d_in[10];
    const float* l1g  = (const float*)d_in[11];
    const float* l1b  = (const float*)d_in[12];
    const float* l2g  = (const float*)d_in[13];
    const float* l2b  = (const float*)d_in[14];
    float* out = (float*)d_out;
    int n = in_sizes[0] / 128;

    cudaFuncSetAttribute(tb_main, cudaFuncAttributeMaxDynamicSharedMemorySize, SMEM_TOT);
    int nsm = 148;
    cudaDeviceGetAttribute(&nsm, cudaDevAttrMultiProcessorCount, 0);

    tb_main<<<nsm, 256, SMEM_TOT>>>(x, knn, xyz, q_w, q_b, k_w, k_b, v_w, v_b,
                                    lw, lb, l1g, l1b, l2g, l2b, out, n);
}